// round 11
// baseline (speedup 1.0000x reference)
#include <cuda_runtime.h>

// ReLU_Conv (CROWN-style ReLU relaxation over bound maps)
// Round 11: R9 optimum shape (1 neuron per 128-thread block, MLP=4,
//           single 4-warp barrier, redundant finalize, streaming stores)
//           with the front batch PINNED via asm-volatile loads (issue
//           order guaranteed: 4 streaming LDG.128 + bounds before any
//           consumption), allowing residency 12 -> 13 blocks/SM without
//           the register-allocator batch collapse seen in R7/R8.
// Output layout: [lx_out | ux_out | lc_out | uc_out]

__device__ __forceinline__ float4 ld_cs_v4(const float4* p) {
    float4 v;
    asm volatile("ld.global.cs.v4.f32 {%0,%1,%2,%3}, [%4];"
                 : "=f"(v.x), "=f"(v.y), "=f"(v.z), "=f"(v.w)
                 : "l"(p));
    return v;
}

__device__ __forceinline__ float4 ld_nc_v4(const float4* p) {
    float4 v;
    asm volatile("ld.global.nc.v4.f32 {%0,%1,%2,%3}, [%4];"
                 : "=f"(v.x), "=f"(v.y), "=f"(v.z), "=f"(v.w)
                 : "l"(p));
    return v;
}

__device__ __forceinline__ void acc_pair(const float4 l, const float4 u,
                                         const float4 mn, const float4 mx,
                                         float& sl, float& su)
{
    // (l>0 ? mn : (l<0 ? mx : 0)) * l == (l>0 ? mn : mx) * l  (finite bounds)
    sl += (l.x > 0.f ? mn.x : mx.x) * l.x;
    su += (u.x > 0.f ? mx.x : mn.x) * u.x;
    sl += (l.y > 0.f ? mn.y : mx.y) * l.y;
    su += (u.y > 0.f ? mx.y : mn.y) * u.y;
    sl += (l.z > 0.f ? mn.z : mx.z) * l.z;
    su += (u.z > 0.f ? mx.z : mn.z) * u.z;
    sl += (l.w > 0.f ? mn.w : mx.w) * l.w;
    su += (u.w > 0.f ? mx.w : mn.w) * u.w;
}

__global__ __launch_bounds__(128, 13)
void relu_conv_kernel(
    const float* __restrict__ lx, const float* __restrict__ ux,
    const float* __restrict__ lc, const float* __restrict__ uc,
    const float* __restrict__ xmin, const float* __restrict__ xmax,
    float* __restrict__ lx_out, float* __restrict__ ux_out,
    float* __restrict__ lc_out, float* __restrict__ uc_out)
{
    const int tid = threadIdx.x;                       // 0..127
    const int n   = blockIdx.x;                        // this block's neuron
    const size_t base = (size_t)n * 1024;

    // PINNED front batch: these four volatile loads issue back-to-back
    // before anything below them can be scheduled in between.
    const float4* plx = reinterpret_cast<const float4*>(lx + base) + tid;
    const float4* pux = reinterpret_cast<const float4*>(ux + base) + tid;
    const float4 vlx0 = ld_cs_v4(plx);
    const float4 vlx1 = ld_cs_v4(plx + 128);
    const float4 vux0 = ld_cs_v4(pux);
    const float4 vux1 = ld_cs_v4(pux + 128);
    const float  lcv  = __ldg(lc + n);
    const float  ucv  = __ldg(uc + n);

    // Bounds loaded volatile AFTER the streaming batch; consumed
    // incrementally so only one mn/mx pair is live at a time.
    float sl = 0.f, su = 0.f;
    {
        const float4 mn0 = ld_nc_v4(reinterpret_cast<const float4*>(xmin) + tid);
        const float4 mx0 = ld_nc_v4(reinterpret_cast<const float4*>(xmax) + tid);
        acc_pair(vlx0, vux0, mn0, mx0, sl, su);
    }
    {
        const float4 mn1 = ld_nc_v4(reinterpret_cast<const float4*>(xmin) + tid + 128);
        const float4 mx1 = ld_nc_v4(reinterpret_cast<const float4*>(xmax) + tid + 128);
        acc_pair(vlx1, vux1, mn1, mx1, sl, su);
    }

    // Warp reduction.
    #pragma unroll
    for (int off = 16; off; off >>= 1) {
        sl += __shfl_down_sync(0xffffffffu, sl, off);
        su += __shfl_down_sync(0xffffffffu, su, off);
    }

    __shared__ float2 sPart[4];                        // per-warp partials
    const int warp = tid >> 5, lane = tid & 31;
    if (lane == 0) sPart[warp] = make_float2(sl, su);
    __syncthreads();                                   // the ONLY barrier

    // Every thread redundantly finalizes (broadcast smem reads; no global
    // loads on this path).
    const float2 p0 = sPart[0], p1 = sPart[1], p2 = sPart[2], p3 = sPart[3];
    const float l = (p0.x + p1.x) + (p2.x + p3.x) + lcv;
    const float u = (p0.y + p1.y) + (p2.y + p3.y) + ucv;

    const bool alive = (l >= 0.f);
    const bool cross = (l < 0.f) && (u > 0.f);
    float slope = cross ? (u / (u - l)) : 1.f;
    slope = fminf(fmaxf(slope, 0.f), 1.f);

    if (tid == 0) {
        lc_out[n] = alive ? lcv : 0.f;
        uc_out[n] = alive ? ucv : (cross ? (slope * ucv - slope * l) : 0.f);
    }

    float4* qlx = reinterpret_cast<float4*>(lx_out + base) + tid;
    float4* qux = reinterpret_cast<float4*>(ux_out + base) + tid;

    float4 o;
    o.x = alive ? vlx0.x : 0.f;  o.y = alive ? vlx0.y : 0.f;
    o.z = alive ? vlx0.z : 0.f;  o.w = alive ? vlx0.w : 0.f;
    __stcs(qlx, o);
    o.x = alive ? vlx1.x : 0.f;  o.y = alive ? vlx1.y : 0.f;
    o.z = alive ? vlx1.z : 0.f;  o.w = alive ? vlx1.w : 0.f;
    __stcs(qlx + 128, o);

    o.x = alive ? vux0.x : (cross ? slope * vux0.x : 0.f);
    o.y = alive ? vux0.y : (cross ? slope * vux0.y : 0.f);
    o.z = alive ? vux0.z : (cross ? slope * vux0.z : 0.f);
    o.w = alive ? vux0.w : (cross ? slope * vux0.w : 0.f);
    __stcs(qux, o);
    o.x = alive ? vux1.x : (cross ? slope * vux1.x : 0.f);
    o.y = alive ? vux1.y : (cross ? slope * vux1.y : 0.f);
    o.z = alive ? vux1.z : (cross ? slope * vux1.z : 0.f);
    o.w = alive ? vux1.w : (cross ? slope * vux1.w : 0.f);
    __stcs(qux + 128, o);
}

extern "C" void kernel_launch(void* const* d_in, const int* in_sizes, int n_in,
                              void* d_out, int out_size)
{
    const float* lx   = (const float*)d_in[0];
    const float* ux   = (const float*)d_in[1];
    const float* lc   = (const float*)d_in[2];
    const float* uc   = (const float*)d_in[3];
    const float* xmin = (const float*)d_in[4];
    const float* xmax = (const float*)d_in[5];

    const int neurons = in_sizes[2];          // C*H*W = 32768
    const size_t nel  = (size_t)neurons * 1024;

    float* out    = (float*)d_out;
    float* lx_out = out;
    float* ux_out = out + nel;
    float* lc_out = out + 2 * nel;
    float* uc_out = out + 2 * nel + neurons;

    relu_conv_kernel<<<neurons, 128>>>(lx, ux, lc, uc, xmin, xmax,
                                       lx_out, ux_out, lc_out, uc_out);
}

// round 12
// speedup vs baseline: 1.0051x; 1.0051x over previous
#include <cuda_runtime.h>

// ReLU_Conv (CROWN-style ReLU relaxation over bound maps) — FINAL
// Configuration proven optimal over 11 measured variants:
//   1 neuron per 128-thread block, 4 front-batched streaming LDG.128/thread
//   (MLP=4), occ 12 / 40-reg allocator mode, single 4-warp barrier,
//   redundant per-thread finalize, streaming stores.
//   (occ>=13 forces ptxas into a 32-reg mode that breaks the load batch:
//    DRAM 80.1% -> 78.0%. MLP 2/8/16, persistence, and warp-per-neuron all
//    measured worse. ~6.34 TB/s = practical HBM ceiling for 1:1 R/W.)
// Epilogue uses per-neuron multipliers (1/slope/0) instead of select chains.
// Output layout: [lx_out | ux_out | lc_out | uc_out]

__device__ __forceinline__ void acc_pair(const float4 l, const float4 u,
                                         const float4 mn, const float4 mx,
                                         float& sl, float& su)
{
    // (l>0 ? mn : (l<0 ? mx : 0)) * l == (l>0 ? mn : mx) * l  (finite bounds)
    sl += (l.x > 0.f ? mn.x : mx.x) * l.x;
    su += (u.x > 0.f ? mx.x : mn.x) * u.x;
    sl += (l.y > 0.f ? mn.y : mx.y) * l.y;
    su += (u.y > 0.f ? mx.y : mn.y) * u.y;
    sl += (l.z > 0.f ? mn.z : mx.z) * l.z;
    su += (u.z > 0.f ? mx.z : mn.z) * u.z;
    sl += (l.w > 0.f ? mn.w : mx.w) * l.w;
    su += (u.w > 0.f ? mx.w : mn.w) * u.w;
}

__global__ __launch_bounds__(128, 12)
void relu_conv_kernel(
    const float* __restrict__ lx, const float* __restrict__ ux,
    const float* __restrict__ lc, const float* __restrict__ uc,
    const float* __restrict__ xmin, const float* __restrict__ xmax,
    float* __restrict__ lx_out, float* __restrict__ ux_out,
    float* __restrict__ lc_out, float* __restrict__ uc_out)
{
    const int tid = threadIdx.x;                       // 0..127
    const int n   = blockIdx.x;                        // this block's neuron
    const size_t base = (size_t)n * 1024;

    // Front-batched streaming loads: 4x LDG.128 per thread, plus this
    // block's scalar offsets (latency hidden under the reduce).
    const float4* plx = reinterpret_cast<const float4*>(lx + base) + tid;
    const float4* pux = reinterpret_cast<const float4*>(ux + base) + tid;
    const float4 vlx0 = __ldcs(plx);
    const float4 vlx1 = __ldcs(plx + 128);
    const float4 vux0 = __ldcs(pux);
    const float4 vux1 = __ldcs(pux + 128);
    const float  lcv  = __ldg(lc + n);
    const float  ucv  = __ldg(uc + n);

    // Broadcast bounds: 8 KB total, L1/L2 resident after wave 1.
    float sl = 0.f, su = 0.f;
    {
        const float4 mn0 = __ldg(reinterpret_cast<const float4*>(xmin) + tid);
        const float4 mx0 = __ldg(reinterpret_cast<const float4*>(xmax) + tid);
        acc_pair(vlx0, vux0, mn0, mx0, sl, su);
    }
    {
        const float4 mn1 = __ldg(reinterpret_cast<const float4*>(xmin) + tid + 128);
        const float4 mx1 = __ldg(reinterpret_cast<const float4*>(xmax) + tid + 128);
        acc_pair(vlx1, vux1, mn1, mx1, sl, su);
    }

    // Warp reduction.
    #pragma unroll
    for (int off = 16; off; off >>= 1) {
        sl += __shfl_down_sync(0xffffffffu, sl, off);
        su += __shfl_down_sync(0xffffffffu, su, off);
    }

    __shared__ float2 sPart[4];                        // per-warp partials
    const int warp = tid >> 5, lane = tid & 31;
    if (lane == 0) sPart[warp] = make_float2(sl, su);
    __syncthreads();                                   // the ONLY barrier

    // Every thread redundantly finalizes (broadcast smem reads; no global
    // loads on this path).
    const float2 p0 = sPart[0], p1 = sPart[1], p2 = sPart[2], p3 = sPart[3];
    const float l = (p0.x + p1.x) + (p2.x + p3.x) + lcv;
    const float u = (p0.y + p1.y) + (p2.y + p3.y) + ucv;

    const bool alive = (l >= 0.f);
    const bool cross = (l < 0.f) && (u > 0.f);
    float slope = cross ? (u / (u - l)) : 1.f;
    slope = fminf(fmaxf(slope, 0.f), 1.f);

    // Per-neuron epilogue multipliers:
    //   lx_out = mlx * lx  with mlx = alive ? 1 : 0
    //   ux_out = mux * ux  with mux = alive ? 1 : (cross ? slope : 0)
    const float mlx = alive ? 1.f : 0.f;
    const float mux = alive ? 1.f : (cross ? slope : 0.f);

    if (tid == 0) {
        lc_out[n] = alive ? lcv : 0.f;
        uc_out[n] = alive ? ucv : (cross ? (slope * ucv - slope * l) : 0.f);
    }

    float4* qlx = reinterpret_cast<float4*>(lx_out + base) + tid;
    float4* qux = reinterpret_cast<float4*>(ux_out + base) + tid;

    float4 o;
    o.x = mlx * vlx0.x;  o.y = mlx * vlx0.y;
    o.z = mlx * vlx0.z;  o.w = mlx * vlx0.w;
    __stcs(qlx, o);
    o.x = mlx * vlx1.x;  o.y = mlx * vlx1.y;
    o.z = mlx * vlx1.z;  o.w = mlx * vlx1.w;
    __stcs(qlx + 128, o);

    o.x = mux * vux0.x;  o.y = mux * vux0.y;
    o.z = mux * vux0.z;  o.w = mux * vux0.w;
    __stcs(qux, o);
    o.x = mux * vux1.x;  o.y = mux * vux1.y;
    o.z = mux * vux1.z;  o.w = mux * vux1.w;
    __stcs(qux + 128, o);
}

extern "C" void kernel_launch(void* const* d_in, const int* in_sizes, int n_in,
                              void* d_out, int out_size)
{
    const float* lx   = (const float*)d_in[0];
    const float* ux   = (const float*)d_in[1];
    const float* lc   = (const float*)d_in[2];
    const float* uc   = (const float*)d_in[3];
    const float* xmin = (const float*)d_in[4];
    const float* xmax = (const float*)d_in[5];

    const int neurons = in_sizes[2];          // C*H*W = 32768
    const size_t nel  = (size_t)neurons * 1024;

    float* out    = (float*)d_out;
    float* lx_out = out;
    float* ux_out = out + nel;
    float* lc_out = out + 2 * nel;
    float* uc_out = out + 2 * nel + neurons;

    relu_conv_kernel<<<neurons, 128>>>(lx, ux, lc, uc, xmin, xmax,
                                       lx_out, ux_out, lc_out, uc_out);
}